// round 9
// baseline (speedup 1.0000x reference)
#include <cuda_runtime.h>

// YOLOLoss fused, round 9: 296 blocks (2/SM exactly) x 256 threads.
// Dense: 4 independent float4 quads per thread (MLP=4), flat task space over
// all 96 conf channel-rows. Targets: blocks 0..31 (batch = blockIdx.x), warps
// 0-1 only, named barrier. Tail: g_part[32][8] fan-out + 296-op counter.

#define BSZ     32
#define NT      50
#define HH      104
#define WW      104
#define HW      (HH*WW)                 // 10816
#define NCLS    20
#define QPC     (HW/4)                  // 2704 quads per conf channel-row
#define TQ      (96*QPC)                // 259584 total quads (32 batches x 3 anchors)
#define NBLK    296                     // 2 blocks per SM, single config wave
#define STRIDE  (NBLK*256)              // 75776 threads
#define KQ      4                       // quads per thread (covers 303104 >= TQ)
#define NCELL   ((double)(BSZ * 3 * HW))

__device__ double   g_part[BSZ][8];     // zero-init; reset by finalizer
__device__ unsigned g_ctr;

// min(softplus(z), 100) == -clip(log(1-sigmoid(z)), -100); spl(-z) == -clip(log(sigmoid(z)), -100)
__device__ __forceinline__ float spl(float z) {
    return fminf(__logf(1.0f + __expf(z)), 100.0f);
}

__global__ __launch_bounds__(256)
void yolo_fused(const float* __restrict__ in, const float* __restrict__ tg,
                float* __restrict__ out)
{
    __shared__ float  s_sparse[8];      // sx, sy, sw, sh, scf, sno_adj, scl, np
    __shared__ float  s_no[8];          // per-warp dense partials
    __shared__ int    s_meta[NT];
    __shared__ int    s_last;

    const int tid  = threadIdx.x;
    const int bid  = blockIdx.x;
    const int lane = tid & 31, wrp = tid >> 5;

    // ---- 1. dense loads: 4 independent float4 quads, issued first ----
    const int Qb = bid * 256 + tid;
    float4 v[KQ];
    #pragma unroll
    for (int k = 0; k < KQ; k++) {
        int Q = Qb + k * STRIDE;
        if (Q < TQ) {
            int r = Q / QPC;            // conf channel-row 0..95 -> channel 25r+4
            int o = Q - r * QPC;
            v[k] = *(const float4*)(in + (size_t)(25 * r + 4) * HW + 4 * o);
        }
    }

    // ---- 2. target path: blocks 0..31, warps 0-1 ----
    if (bid < BSZ && tid < 64) {
        const int b = bid;
        const float* base = in + (size_t)b * 75 * HW;
        if (tid < 8) s_sparse[tid] = 0.0f;       // ordered by named barrier below

        int   mymeta = 0x7FFFFFFF;
        float mytx = 0.f, myty = 0.f, mytw = 0.f, myth = 0.f;
        if (tid < NT) {
            const float* t = tg + ((size_t)b * NT + tid) * 5;
            float t0 = t[0], t1 = t[1], t2 = t[2], t3 = t[3], t4 = t[4];
            if (t0 + t1 + t2 + t3 + t4 > 0.0f) {
                float gx = t0 * (float)WW, gy = t1 * (float)HH;
                float gw = t2 * (float)WW, gh = t3 * (float)HH;
                int gi = (int)gx, gj = (int)gy;
                const float aw[3] = {14.5f, 19.5f, 46.625f};   // ANCHORS / 8
                const float ah[3] = {11.25f, 24.75f, 40.75f};
                float area = (gw + 1.0f) * (gh + 1.0f);
                float best = -1.0f; int bn = 0, nz = 0;
                #pragma unroll
                for (int a = 0; a < 3; a++) {
                    float inter = fmaxf(fminf(gw, aw[a]) + 1.0f, 0.0f) *
                                  fmaxf(fminf(gh, ah[a]) + 1.0f, 0.0f);
                    float iou = inter / (area + (aw[a] + 1.0f) * (ah[a] + 1.0f) - inter + 1e-16f);
                    if (iou > best) { best = iou; bn = a; }      // first max wins
                    if (iou > 0.5f) nz |= (1 << a);
                }
                mytx = gx - (float)gi;
                myty = gy - (float)gj;
                mytw = __logf(gw / aw[bn] + 1e-16f);
                myth = __logf(gh / ah[bn] + 1e-16f);
                mymeta = (gj * WW + gi) | (bn << 14) | (nz << 16) | (((int)t4) << 19);
            }
            s_meta[tid] = mymeta;
        }

        // speculative box/conf loads (classes stay post-barrier to cap regs)
        const bool valid = (mymeta != 0x7FFFFFFF);
        float vx = 0, vy = 0, vw = 0, vh = 0, vc = 0, cfa0 = 0, cfa1 = 0, cfa2 = 0;
        int   mypos = 0, mya = 0;
        if (valid) {
            mypos = mymeta & 0x3FFF;
            mya   = (mymeta >> 14) & 3;
            const float* ch = base + (size_t)(mya * 25) * HW + mypos;
            vx = ch[0]; vy = ch[HW]; vw = ch[2 * HW]; vh = ch[3 * HW]; vc = ch[4 * HW];
            cfa0 = base[(size_t)( 4) * HW + mypos];
            cfa1 = base[(size_t)(29) * HW + mypos];
            cfa2 = base[(size_t)(54) * HW + mypos];
        }

        asm volatile("bar.sync 1, 64;" ::: "memory");   // warps 0-1 only

        if (valid) {
            int      mynz  = (mymeta >> 16) & 7;
            unsigned cm    = 1u << ((mymeta >> 19) & 31);
            bool     alive = true;
            int      subnz = mynz;
            for (int u = 0; u < NT; u++) {
                if (u == tid) continue;
                int mu = s_meta[u];
                if ((mu & 0x3FFF) != mypos) continue;            // sentinel never matches
                if (((mu >> 14) & 3) == mya) {
                    if (u > tid) alive = false;                  // last duplicate wins
                    else         cm |= 1u << ((mu >> 19) & 31);  // union earlier classes
                }
                if (u < tid) subnz &= ~((mu >> 16) & 7);         // earliest owner subtracts
            }
            float sub = 0.0f;            // remove ignored cells from dense sum
            if (subnz & 1) sub += spl(cfa0);
            if (subnz & 2) sub += spl(cfa1);
            if (subnz & 4) sub += spl(cfa2);
            if (sub != 0.0f) atomicAdd(&s_sparse[5], -sub);

            if (alive) {
                const float* ch = base + (size_t)(mya * 25) * HW + mypos;
                float pc[NCLS];
                #pragma unroll
                for (int c = 0; c < NCLS; c++) pc[c] = ch[(size_t)(5 + c) * HW];
                float scl = 0.0f;
                #pragma unroll
                for (int c = 0; c < NCLS; c++)
                    scl += spl(((cm >> c) & 1) ? -pc[c] : pc[c]);
                // BCE(sigm(z), t) = t*spl(-z) + (1-t)*spl(z)
                atomicAdd(&s_sparse[0], mytx * spl(-vx) + (1.0f - mytx) * spl(vx));
                atomicAdd(&s_sparse[1], myty * spl(-vy) + (1.0f - myty) * spl(vy));
                float dw = vw - mytw, dh = vh - myth;
                atomicAdd(&s_sparse[2], dw * dw);
                atomicAdd(&s_sparse[3], dh * dh);
                atomicAdd(&s_sparse[4], spl(-vc));
                atomicAdd(&s_sparse[6], scl);
                atomicAdd(&s_sparse[7], 1.0f);
            }
        }
    } else if (tid < 8) {
        s_sparse[tid] = 0.0f;           // non-target blocks: plain zero (pre-syncthreads)
    }

    // ---- 3. dense math (all warps) ----
    float a_no = 0.0f;
    #pragma unroll
    for (int k = 0; k < KQ; k++) {
        int Q = Qb + k * STRIDE;
        if (Q < TQ)
            a_no += spl(v[k].x) + spl(v[k].y) + spl(v[k].z) + spl(v[k].w);
    }
    #pragma unroll
    for (int off = 16; off > 0; off >>= 1)
        a_no += __shfl_down_sync(0xFFFFFFFFu, a_no, off);
    if (lane == 0) s_no[wrp] = a_no;    // plain store, own slot

    __syncthreads();                    // only full-block barrier

    // ---- 4. block partial -> fan-out slot (<=10 ops per address) ----
    if (tid < 8) {
        float p = s_sparse[tid];
        if (tid == 5) {
            #pragma unroll
            for (int w8 = 0; w8 < 8; w8++) p += s_no[w8];
        }
        if (p != 0.0f) atomicAdd(&g_part[bid & 31][tid], (double)p);
    }
    __threadfence();
    __syncthreads();
    if (tid == 0) s_last = (atomicAdd(&g_ctr, 1) == NBLK - 1);
    __syncthreads();

    // ---- 5. last block finalizes + resets ----
    if (s_last) {
        __threadfence();
        __shared__ double s_tot[8];
        if (wrp < 8) {
            double vv = atomicAdd(&g_part[lane][wrp], 0.0);  // coherent read
            #pragma unroll
            for (int off = 16; off > 0; off >>= 1)
                vv += __shfl_down_sync(0xFFFFFFFFu, vv, off);
            if (lane == 0) s_tot[wrp] = vv;
            g_part[lane][wrp] = 0.0;                         // reset for next replay
        }
        __syncthreads();
        if (tid == 0) {
            double sx = s_tot[0], sy = s_tot[1], sw = s_tot[2], sh = s_tot[3];
            double scf = s_tot[4], sno = s_tot[5], scl = s_tot[6], np = s_tot[7];
            out[0] = (float)(2.5 * sx / NCELL);
            out[1] = (float)(2.5 * sy / NCELL);
            out[2] = (float)(2.5 * sw / NCELL);
            out[3] = (float)(2.5 * sh / NCELL);
            out[4] = (float)((scf + 0.5 * sno) / NCELL);
            out[5] = (float)(scl / fmax(np * 20.0, 1.0));
            __threadfence();
            g_ctr = 0;
        }
    }
}

extern "C" void kernel_launch(void* const* d_in, const int* in_sizes, int n_in,
                              void* d_out, int out_size) {
    const float* in = (const float*)d_in[0];   // (32,75,104,104)
    const float* tg = (const float*)d_in[1];   // (32,50,5)
    float* out = (float*)d_out;                // 6 floats

    yolo_fused<<<NBLK, 256>>>(in, tg, out);    // 296 blocks = 2 per SM
}

// round 10
// speedup vs baseline: 1.6155x; 1.6155x over previous
#include <cuda_runtime.h>

// YOLOLoss fused, round 10: R4 structure (the measured best) with ONE change:
// dense softplus sum computed as log of products --
//   sum_i softplus(z_i) = log( prod_i (1 + e^{z_i}) )
// 6 elements/thread: 6 EX2 + 1 LG2 = 7 MUFU vs 12. Kernel is MUFU-roofline-bound
// (2.08M MUFU @ 74/cyc = 15.8us == R4 measured), so this cuts the floor ~42%.

#define BSZ     32
#define NT      50
#define HH      104
#define WW      104
#define HW      (HH*WW)                 // 10816
#define NCLS    20
#define BLK_POS 512                     // 256 thr x 2 positions
#define NBX     ((HW + BLK_POS - 1) / BLK_POS)   // 22
#define NBLK    (NBX * BSZ)             // 704
#define NCELL   ((double)(BSZ * 3 * HW))

__device__ double   g_acc[8];           // zero-init; reset by finalizer
__device__ unsigned g_ctr;

// min(softplus(z), 100) == -clip(log(1-sigmoid(z)), -100); spl(-z) == -clip(log(sigmoid(z)), -100)
__device__ __forceinline__ float spl(float z) {
    return fminf(__logf(1.0f + __expf(z)), 100.0f);
}

__global__ __launch_bounds__(256)
void yolo_fused(const float* __restrict__ in, const float* __restrict__ tg,
                float* __restrict__ out)
{
    __shared__ int   s_meta[NT];        // pos(14)|bn(2)|nz(3)|cls(5)
    __shared__ float s_acc[8];
    __shared__ int   s_last;

    const int b    = blockIdx.y;
    const int tid  = threadIdx.x;
    const int P0   = blockIdx.x * BLK_POS;
    const int lane = tid & 31;

    // ---- dense conf loads: 2 positions x 3 anchors, issued first ----
    const int  p0   = P0 + tid * 2;
    const bool live = (p0 < HW);        // HW even -> full pairs
    const float* base = in + (size_t)b * 75 * HW;
    float2 c0, c1, c2;
    if (live) {
        c0 = *(const float2*)(base + (size_t)( 4) * HW + p0);
        c1 = *(const float2*)(base + (size_t)(29) * HW + p0);
        c2 = *(const float2*)(base + (size_t)(54) * HW + p0);
    }
    if (tid < 8) s_acc[tid] = 0.0f;

    // ---- per-target prologue (threads 0..49), own meta kept in registers ----
    int  mymeta = 0;
    bool inr = false;
    float mytx = 0.f, myty = 0.f, mytw = 0.f, myth = 0.f;
    if (tid < NT) {
        const float* t = tg + ((size_t)b * NT + tid) * 5;
        float t0 = t[0], t1 = t[1], t2 = t[2], t3 = t[3], t4 = t[4];
        int meta = 0x7FFFFFFF;          // invalid: low14 = 16383 > any pos
        if (t0 + t1 + t2 + t3 + t4 > 0.0f) {
            float gx = t0 * (float)WW, gy = t1 * (float)HH;
            float gw = t2 * (float)WW, gh = t3 * (float)HH;
            int gi = (int)gx, gj = (int)gy;
            const float aw[3] = {14.5f, 19.5f, 46.625f};   // ANCHORS / 8
            const float ah[3] = {11.25f, 24.75f, 40.75f};
            float area = (gw + 1.0f) * (gh + 1.0f);
            float best = -1.0f; int bn = 0, nz = 0;
            #pragma unroll
            for (int a = 0; a < 3; a++) {
                float inter = fmaxf(fminf(gw, aw[a]) + 1.0f, 0.0f) *
                              fmaxf(fminf(gh, ah[a]) + 1.0f, 0.0f);
                float iou = inter / (area + (aw[a] + 1.0f) * (ah[a] + 1.0f) - inter + 1e-16f);
                if (iou > best) { best = iou; bn = a; }      // first max wins
                if (iou > 0.5f) nz |= (1 << a);
            }
            mytx = gx - (float)gi;
            myty = gy - (float)gj;
            mytw = __logf(gw / aw[bn] + 1e-16f);
            myth = __logf(gh / ah[bn] + 1e-16f);
            int pos = gj * WW + gi;
            meta = pos | (bn << 14) | (nz << 16) | (((int)t4) << 19);
            inr = (pos >= P0) && (pos < P0 + BLK_POS);
        }
        s_meta[tid] = meta;
        mymeta = meta;
    }

    // ---- speculative loads for in-range targets (pre-barrier) ----
    float vx = 0, vy = 0, vw = 0, vh = 0, vc = 0, cfa0 = 0, cfa1 = 0, cfa2 = 0;
    int   mypos = 0, mya = 0;
    if (inr) {
        mypos = mymeta & 0x3FFF;
        mya   = (mymeta >> 14) & 3;
        const float* ch = base + (size_t)(mya * 25) * HW + mypos;
        vx = ch[0]; vy = ch[HW]; vw = ch[2 * HW]; vh = ch[3 * HW]; vc = ch[4 * HW];
        cfa0 = base[(size_t)( 4) * HW + mypos];
        cfa1 = base[(size_t)(29) * HW + mypos];
        cfa2 = base[(size_t)(54) * HW + mypos];
    }

    // ---- dense math: log of products (6 EX2 + 1 LG2 instead of 12 MUFU) ----
    float a_no = 0.0f;
    if (live) {
        float e0 = __expf(c0.x), e1 = __expf(c0.y);
        float e2 = __expf(c1.x), e3 = __expf(c1.y);
        float e4 = __expf(c2.x), e5 = __expf(c2.y);
        float P = (1.0f + e0);
        P = fmaf(P, e1, P);             // P *= (1+e1)
        P = fmaf(P, e2, P);
        P = fmaf(P, e3, P);
        P = fmaf(P, e4, P);
        P = fmaf(P, e5, P);
        a_no = __logf(P);               // == sum of 6 softplus values
    }
    #pragma unroll
    for (int off = 16; off > 0; off >>= 1)
        a_no += __shfl_down_sync(0xFFFFFFFFu, a_no, off);

    __syncthreads();                    // orders s_acc zero + s_meta
    if (lane == 0 && a_no != 0.0f) atomicAdd(&s_acc[5], a_no);

    // ---- target resolution: dedup survivors, class union, unique ignore bits ----
    if (inr) {
        int      mynz  = (mymeta >> 16) & 7;
        unsigned cm    = 1u << ((mymeta >> 19) & 31);
        bool     alive = true;
        int      subnz = mynz;
        for (int u = 0; u < NT; u++) {
            if (u == tid) continue;
            int mu = s_meta[u];
            if ((mu & 0x3FFF) != mypos) continue;
            if (((mu >> 14) & 3) == mya) {
                if (u > tid) alive = false;                  // last duplicate wins
                else         cm |= 1u << ((mu >> 19) & 31);  // union earlier classes
            }
            if (u < tid) subnz &= ~((mu >> 16) & 7);         // earlier owner subtracts
        }
        float sub = 0.0f;               // remove ignored cells from dense sum
        if (subnz & 1) sub += spl(cfa0);
        if (subnz & 2) sub += spl(cfa1);
        if (subnz & 4) sub += spl(cfa2);
        if (sub != 0.0f) atomicAdd(&s_acc[5], -sub);

        if (alive) {
            const float* ch = base + (size_t)(mya * 25) * HW + mypos;
            float pc[NCLS];
            #pragma unroll
            for (int c = 0; c < NCLS; c++) pc[c] = ch[(size_t)(5 + c) * HW];
            float scl = 0.0f;
            #pragma unroll
            for (int c = 0; c < NCLS; c++)
                scl += spl(((cm >> c) & 1) ? -pc[c] : pc[c]);
            // BCE(sigm(z), t) = t*spl(-z) + (1-t)*spl(z)
            atomicAdd(&s_acc[0], mytx * spl(-vx) + (1.0f - mytx) * spl(vx));
            atomicAdd(&s_acc[1], myty * spl(-vy) + (1.0f - myty) * spl(vy));
            float dw = vw - mytw, dh = vh - myth;
            atomicAdd(&s_acc[2], dw * dw);
            atomicAdd(&s_acc[3], dh * dh);
            atomicAdd(&s_acc[4], spl(-vc));
            atomicAdd(&s_acc[6], scl);
            atomicAdd(&s_acc[7], 1.0f);
        }
    }
    __syncthreads();

    // ---- global accumulation + last-block finalize ----
    if (tid < 8) {
        float v = s_acc[tid];
        if (v != 0.0f) atomicAdd(&g_acc[tid], (double)v);
    }
    __threadfence();
    __syncthreads();
    if (tid == 0) s_last = (atomicAdd(&g_ctr, 1) == NBLK - 1);
    __syncthreads();

    if (s_last && tid == 0) {
        __threadfence();
        double A[8];
        #pragma unroll
        for (int i = 0; i < 8; i++) A[i] = atomicAdd(&g_acc[i], 0.0);  // coherent read
        out[0] = (float)(2.5 * A[0] / NCELL);
        out[1] = (float)(2.5 * A[1] / NCELL);
        out[2] = (float)(2.5 * A[2] / NCELL);
        out[3] = (float)(2.5 * A[3] / NCELL);
        out[4] = (float)((A[4] + 0.5 * A[5]) / NCELL);
        out[5] = (float)(A[6] / fmax(A[7] * 20.0, 1.0));
        #pragma unroll
        for (int i = 0; i < 8; i++) g_acc[i] = 0.0;    // reset for next replay
        __threadfence();
        g_ctr = 0;
    }
}

extern "C" void kernel_launch(void* const* d_in, const int* in_sizes, int n_in,
                              void* d_out, int out_size) {
    const float* in = (const float*)d_in[0];   // (32,75,104,104)
    const float* tg = (const float*)d_in[1];   // (32,50,5)
    float* out = (float*)d_out;                // 6 floats

    dim3 grid(NBX, BSZ);                       // (22, 32) = 704 blocks
    yolo_fused<<<grid, 256>>>(in, tg, out);
}